// round 1
// baseline (speedup 1.0000x reference)
#include <cuda_runtime.h>

// x: (B=8, C=16, T=2000, F=128) fp32, contiguous.
// For each (b,c,f) column (stride F along t):
//   block sums over POOL=10, causal cumulative mean/var over blocks, normalize.
// Single pass: one thread per column, block buffered in registers,
// 2-block-deep register prefetch pipeline for memory-level parallelism.

#define TT   2000
#define FF   128
#define PP   10
#define TT1  200
#define EPSV 1e-5f

__global__ void __launch_bounds__(128, 1)
inorm_kernel(const float* __restrict__ x, float* __restrict__ out)
{
    const int col = blockIdx.x;          // b*C + c  (0..127)
    const int f   = threadIdx.x;         // 0..127

    const float* p = x   + (size_t)col * TT * FF + f;
    float*       o = out + (size_t)col * TT * FF + f;

    float a0[PP], a1[PP], a2[PP];

    // Prologue: prefetch blocks 0 and 1
    #pragma unroll
    for (int i = 0; i < PP; i++) a0[i] = p[i * FF];
    #pragma unroll
    for (int i = 0; i < PP; i++) a1[i] = p[(PP + i) * FF];
    p += 2 * PP * FF;

    float s = 0.f, s2 = 0.f;

    #pragma unroll 1
    for (int k = 0; k < TT1; k++) {
        // Prefetch block k+2 (issued before any use of a0 -> overlaps compute+stores)
        if (k + 2 < TT1) {
            #pragma unroll
            for (int i = 0; i < PP; i++) a2[i] = p[i * FF];
            p += PP * FF;
        }

        // Block sums of current block (a0)
        float bs = 0.f, bs2 = 0.f;
        #pragma unroll
        for (int i = 0; i < PP; i++) {
            bs  += a0[i];
            bs2  = fmaf(a0[i], a0[i], bs2);
        }
        s  += bs;
        s2 += bs2;

        // Causal cumulative mean / var over elements seen so far: n = (k+1)*POOL
        const float invn = __fdividef(1.0f, (float)((k + 1) * PP));
        const float m  = s  * invn;
        const float m2 = s2 * invn;
        const float v  = fmaf(-m, m, m2);
        const float r  = rsqrtf(v + EPSV);

        // Normalize + write current block
        #pragma unroll
        for (int i = 0; i < PP; i++)
            o[i * FF] = (a0[i] - m) * r;
        o += PP * FF;

        // Rotate pipeline
        #pragma unroll
        for (int i = 0; i < PP; i++) { a0[i] = a1[i]; a1[i] = a2[i]; }
    }
}

extern "C" void kernel_launch(void* const* d_in, const int* in_sizes, int n_in,
                              void* d_out, int out_size)
{
    const float* x   = (const float*)d_in[0];
    float*       out = (float*)d_out;
    // B*C = 128 columns of (T=2000, F=128)
    inorm_kernel<<<128, 128>>>(x, out);
}

// round 2
// speedup vs baseline: 2.3405x; 2.3405x over previous
#include <cuda_runtime.h>
#include <cstdint>

// x: (B=8, C=16, T=2000, F=128) fp32.
// Per (b,c,f) column: POOL=10 block sums, causal cumulative mean/var, normalize.
// Single pass. cp.async ring buffer (depth 8 blocks) in shared memory gives
// compiler-proof MLP; grid = 128 columns x 4 f-quarters = 512 CTAs of 32 threads.

#define TT    2000
#define FF    128
#define PP    10
#define TT1   200
#define DD    8          // ring depth in pooled blocks
#define EPSV  1e-5f

__device__ __forceinline__ void cp4(uint32_t saddr, const float* gaddr) {
    asm volatile("cp.async.ca.shared.global [%0], [%1], 4;\n"
                 :: "r"(saddr), "l"(gaddr));
}
#define CP_COMMIT() asm volatile("cp.async.commit_group;\n")
#define CP_WAIT(n)  asm volatile("cp.async.wait_group %0;\n" :: "n"(n))

__global__ void __launch_bounds__(32, 4)
inorm_kernel(const float* __restrict__ x, float* __restrict__ out)
{
    __shared__ float buf[DD][PP][32];   // 10240 B

    const int col  = blockIdx.x >> 2;                     // (b*C + c): 0..127
    const int f    = ((blockIdx.x & 3) << 5) + threadIdx.x;  // 0..127
    const int lane = threadIdx.x;

    const float* p = x   + (size_t)col * TT * FF + f;
    float*       o = out + (size_t)col * TT * FF + f;

    uint32_t sbase;
    asm("{ .reg .u64 t; cvta.to.shared.u64 t, %1; cvt.u32.u64 %0, t; }"
        : "=r"(sbase) : "l"(&buf[0][0][lane]));
    // strides in bytes: block i -> 32*4 = 128, stage -> PP*32*4 = 1280

    // Prologue: fill the ring with blocks 0..DD-1 (one commit group per stage)
    #pragma unroll
    for (int st = 0; st < DD; st++) {
        #pragma unroll
        for (int i = 0; i < PP; i++)
            cp4(sbase + st * 1280 + i * 128, p + (st * PP + i) * FF);
        CP_COMMIT();
    }

    float s = 0.f, s2 = 0.f;

    #pragma unroll 1
    for (int kk = 0; kk < TT1; kk += DD) {
        #pragma unroll
        for (int st = 0; st < DD; st++) {
            const int k = kk + st;

            // Ensure stage k (the oldest of DD pending groups) has landed.
            CP_WAIT(DD - 1);

            // Consume block k from its ring slot.
            float a[PP];
            #pragma unroll
            for (int i = 0; i < PP; i++)
                a[i] = buf[st][i][lane];

            // Refill this slot with block k+DD, then commit (always commit,
            // empty groups in the tail keep the group count consistent).
            const int kn = k + DD;
            if (kn < TT1) {
                const float* pg = p + kn * PP * FF;
                #pragma unroll
                for (int i = 0; i < PP; i++)
                    cp4(sbase + st * 1280 + i * 128, pg + i * FF);
            }
            CP_COMMIT();

            // Block sums + causal running stats
            float bs = 0.f, bs2 = 0.f;
            #pragma unroll
            for (int i = 0; i < PP; i++) {
                bs  += a[i];
                bs2  = fmaf(a[i], a[i], bs2);
            }
            s  += bs;
            s2 += bs2;

            const float invn = __fdividef(1.0f, (float)((k + 1) * PP));
            const float m    = s  * invn;
            const float m2   = s2 * invn;
            const float v    = fmaf(-m, m, m2);
            const float r    = rsqrtf(v + EPSV);

            float* og = o + k * PP * FF;
            #pragma unroll
            for (int i = 0; i < PP; i++)
                og[i * FF] = (a[i] - m) * r;
        }
    }
}

extern "C" void kernel_launch(void* const* d_in, const int* in_sizes, int n_in,
                              void* d_out, int out_size)
{
    const float* x   = (const float*)d_in[0];
    float*       out = (float*)d_out;
    inorm_kernel<<<512, 32>>>(x, out);
}